// round 14
// baseline (speedup 1.0000x reference)
#include <cuda_runtime.h>
#include <cuda_fp16.h>

#define HID   51
#define TT    2048
#define NN    1024
#define CHUNK 64
#define NTH   64          // 2 warps; warp w owns units [26w, 26w+26); 2 seqs/block

__device__ __forceinline__ float tanhx(float x) {
    float r; asm("tanh.approx.f32 %0, %1;" : "=f"(r) : "f"(x)); return r;
}

__global__ void __launch_bounds__(NTH, 4)
lstm2_kernel(const float* __restrict__ stim,
             const float* __restrict__ Wih1,   // (204,1)
             const float* __restrict__ Whh1,   // (204,51)
             const float* __restrict__ bih1,
             const float* __restrict__ bhh1,
             const float* __restrict__ Wih2,   // (4,51)
             const float* __restrict__ Whh2,   // (4,1)
             const float* __restrict__ bih2,
             const float* __restrict__ bhh2,
             float* __restrict__ out)          // (1024,2048)
{
    __shared__ __align__(16) __half2 hbuf[2][52];   // h as (seqA,seqB); [51]=0 pad
    __shared__ __align__(16) unsigned gacc[208];    // warp0: 0..103, warp1: 104..207
    __shared__ __align__(16) float x_sh[2][CHUNK];
    __shared__ __align__(16) float ob_sh[2][CHUNK];

    const int tid = threadIdx.x;
    const int w   = tid >> 5;
    const int l   = tid & 31;
    const int n0  = blockIdx.x * 2;

    // ---- matvec rows: ri = l + 32*i (i=0..3), valid if ri<104 ----------
    // row ri -> unit u = 26w + (ri>>2), gate g = ri&3
    __half2 wpk[4][26];
#pragma unroll
    for (int i = 0; i < 4; i++)
#pragma unroll
        for (int kk = 0; kk < 26; kk++) wpk[i][kk] = __half2half2(__ushort_as_half(0));
#pragma unroll
    for (int i = 0; i < 4; i++) {
        int ri = l + 32 * i;
        if (ri < 104) {
            int u = 26 * w + (ri >> 2), g = ri & 3;
            const float* src = (u < HID) ? (Whh1 + (g * HID + u) * HID)
                                         : (Wih2 + g * HID);
#pragma unroll
            for (int kk = 0; kk < 26; kk++) {
                float a = src[2*kk];
                float b = (2*kk + 1 < HID) ? src[2*kk + 1] : 0.f;
                wpk[i][kk] = __floats2half2_rn(a, b);
            }
        }
    }

    // ---- owner: lane l<26 owns unit u = 26w + l -------------------------
    const bool owner = (l < 26);
    const int  uown  = 26 * w + l;
    const bool isl2  = (uown == HID);      // warp 1, lane 25
    float bias[4], wi[4];
#pragma unroll
    for (int g = 0; g < 4; g++) {
        if (owner) {
            if (isl2) { bias[g] = bih2[g] + bhh2[g]; wi[g] = Whh2[g]; }
            else {
                int row = g * HID + uown;
                bias[g] = bih1[row] + bhh1[row];
                wi[g]   = Wih1[row];
            }
        } else { bias[g] = 0.f; wi[g] = 0.f; }
    }

    for (int i = tid; i < 104; i += NTH) ((unsigned*)hbuf)[i] = 0u;
    float c0 = 0.f, c1 = 0.f;          // owned unit cell states, seq 0/1
    float h2a = 0.f, h2b = 0.f;        // layer-2 hidden (isl2 owner only)

    if (tid < 32) {
        int s = tid >> 4, q = (tid & 15) * 4;
        *(float4*)&x_sh[s][q] = *(const float4*)&stim[(n0 + s) * TT + q];
    }
    __syncthreads();

#pragma unroll 1
    for (int t0 = 0; t0 < TT; t0 += CHUNK) {
#pragma unroll 2
        for (int dt = 0; dt < CHUNK; dt++) {
            const int rd = dt & 1;
            // ---- seq-packed matvec: 208 HFMA2 for 2 seqs ---------------
            __half2 z = __half2half2(__ushort_as_half(0));
            __half2 a1[4] = {z,z,z,z}, a2[4] = {z,z,z,z};
            const uint4* h4 = (const uint4*)&hbuf[rd][0];
#pragma unroll
            for (int q = 0; q < 13; q++) {
                uint4 v = h4[q];
                __half2 p0 = *(__half2*)&v.x, p1 = *(__half2*)&v.y;
                __half2 p2 = *(__half2*)&v.z, p3 = *(__half2*)&v.w;
#pragma unroll
                for (int i = 0; i < 4; i++) {
                    a1[i] = __hfma2(__low2half2 (wpk[i][2*q]),   p0, a1[i]);
                    a2[i] = __hfma2(__high2half2(wpk[i][2*q]),   p1, a2[i]);
                    a1[i] = __hfma2(__low2half2 (wpk[i][2*q+1]), p2, a1[i]);
                    a2[i] = __hfma2(__high2half2(wpk[i][2*q+1]), p3, a2[i]);
                }
            }
#pragma unroll
            for (int i = 0; i < 4; i++) {
                int ri = l + 32 * i;
                if (ri < 104) {
                    __half2 s2 = __hadd2(a1[i], a2[i]);
                    gacc[w * 104 + ri] = *(unsigned*)&s2;
                }
            }
            __syncwarp();

            // ---- owner phase: fp32 gate finish + cell update -----------
            if (owner) {
                uint4 g4 = *(const uint4*)&gacc[w * 104 + l * 4];
                float2 fi = __half22float2(*(__half2*)&g4.x);
                float2 ff = __half22float2(*(__half2*)&g4.y);
                float2 fg = __half22float2(*(__half2*)&g4.z);
                float2 fo = __half22float2(*(__half2*)&g4.w);
                float xa = isl2 ? h2a : x_sh[0][dt];
                float xb = isl2 ? h2b : x_sh[1][dt];
                float i0 = fi.x + fmaf(wi[0], xa, bias[0]);
                float f0 = ff.x + fmaf(wi[1], xa, bias[1]);
                float g0 = fg.x + fmaf(wi[2], xa, bias[2]);
                float o0 = fo.x + fmaf(wi[3], xa, bias[3]);
                float i1 = fi.y + fmaf(wi[0], xb, bias[0]);
                float f1 = ff.y + fmaf(wi[1], xb, bias[1]);
                float g1 = fg.y + fmaf(wi[2], xb, bias[2]);
                float o1 = fo.y + fmaf(wi[3], xb, bias[3]);
                if (!isl2) {
                    c0 = fmaf(fmaf(0.5f, tanhx(0.5f * f0), 0.5f), c0,
                              fmaf(0.5f, tanhx(0.5f * i0), 0.5f) * tanhx(g0));
                    c1 = fmaf(fmaf(0.5f, tanhx(0.5f * f1), 0.5f), c1,
                              fmaf(0.5f, tanhx(0.5f * i1), 0.5f) * tanhx(g1));
                    float h0 = fmaf(0.5f, tanhx(0.5f * o0), 0.5f) * tanhx(c0);
                    float h1 = fmaf(0.5f, tanhx(0.5f * o1), 0.5f) * tanhx(c1);
                    hbuf[1 - rd][uown] = __floats2half2_rn(h0, h1);
                } else if ((t0 | dt) != 0) {       // lag-1 layer-2; skip t=0
                    c0 = fmaf(fmaf(0.5f, tanhx(0.5f * f0), 0.5f), c0,
                              fmaf(0.5f, tanhx(0.5f * i0), 0.5f) * tanhx(g0));
                    c1 = fmaf(fmaf(0.5f, tanhx(0.5f * f1), 0.5f), c1,
                              fmaf(0.5f, tanhx(0.5f * i1), 0.5f) * tanhx(g1));
                    float y0 = fmaf(0.5f, tanhx(0.5f * o0), 0.5f) * tanhx(c0);
                    float y1 = fmaf(0.5f, tanhx(0.5f * o1), 0.5f) * tanhx(c1);
                    ob_sh[0][dt] = y0; h2a = y0;
                    ob_sh[1][dt] = y1; h2b = y1;
                }
            }
            __syncthreads();
        }
        // ---- flush outputs (lagged by 1) + stage next chunk ------------
        for (int i = tid; i < 2 * CHUNK; i += NTH) {
            int s = i >> 6, col = i & 63;
            int tt = t0 - 1 + col;
            if (tt >= 0) out[(n0 + s) * TT + tt] = ob_sh[s][col];
        }
        if (t0 + CHUNK < TT && tid < 32) {
            int s = tid >> 4, q = (tid & 15) * 4;
            *(float4*)&x_sh[s][q] =
                *(const float4*)&stim[(n0 + s) * TT + t0 + CHUNK + q];
        }
        __syncthreads();
    }

    // ---- tail: y(2047) from h1(2047) (in hbuf[0]); L2 owner alone ------
    if (isl2) {
        float gt0[4] = {0.f, 0.f, 0.f, 0.f};
        float gt1[4] = {0.f, 0.f, 0.f, 0.f};
        for (int k = 0; k < HID; k++) {
            float2 hv = __half22float2(hbuf[0][k]);
#pragma unroll
            for (int g = 0; g < 4; g++) {
                float wv = Wih2[g * HID + k];
                gt0[g] = fmaf(wv, hv.x, gt0[g]);
                gt1[g] = fmaf(wv, hv.y, gt1[g]);
            }
        }
#pragma unroll
        for (int g = 0; g < 4; g++) {
            gt0[g] += fmaf(wi[g], h2a, bias[g]);
            gt1[g] += fmaf(wi[g], h2b, bias[g]);
        }
        c0 = fmaf(fmaf(0.5f, tanhx(0.5f * gt0[1]), 0.5f), c0,
                  fmaf(0.5f, tanhx(0.5f * gt0[0]), 0.5f) * tanhx(gt0[2]));
        c1 = fmaf(fmaf(0.5f, tanhx(0.5f * gt1[1]), 0.5f), c1,
                  fmaf(0.5f, tanhx(0.5f * gt1[0]), 0.5f) * tanhx(gt1[2]));
        out[(n0 + 0) * TT + (TT - 1)] =
            fmaf(0.5f, tanhx(0.5f * gt0[3]), 0.5f) * tanhx(c0);
        out[(n0 + 1) * TT + (TT - 1)] =
            fmaf(0.5f, tanhx(0.5f * gt1[3]), 0.5f) * tanhx(c1);
    }
}

extern "C" void kernel_launch(void* const* d_in, const int* in_sizes, int n_in,
                              void* d_out, int out_size)
{
    (void)in_sizes; (void)n_in; (void)out_size;
    const float* stim  = (const float*)d_in[0];
    const float* Wih1  = (const float*)d_in[1];
    const float* Whh1  = (const float*)d_in[2];
    const float* bih1  = (const float*)d_in[3];
    const float* bhh1  = (const float*)d_in[4];
    const float* Wih2  = (const float*)d_in[5];
    const float* Whh2  = (const float*)d_in[6];
    const float* bih2  = (const float*)d_in[7];
    const float* bhh2  = (const float*)d_in[8];
    float* out = (float*)d_out;

    lstm2_kernel<<<NN / 2, NTH>>>(stim, Wih1, Whh1, bih1, bhh1,
                                  Wih2, Whh2, bih2, bhh2, out);
}

// round 15
// speedup vs baseline: 1.7335x; 1.7335x over previous
#include <cuda_runtime.h>
#include <cuda_fp16.h>

#define HID   51
#define TT    2048
#define NN    1024
#define CHUNK 64
#define NROWS 208         // 204 layer-1 gate rows + 4 layer-2 rows; r = u*4+g
#define NTH   32          // ONE warp per block, one sequence per block

__device__ __forceinline__ float tanhx(float x) {
    float r; asm("tanh.approx.f32 %0, %1;" : "=f"(r) : "f"(x)); return r;
}
__device__ __forceinline__ __half hsum2(__half2 v) {
    return __hadd(__low2half(v), __high2half(v));
}

__global__ void __launch_bounds__(NTH)
lstm2_kernel(const float* __restrict__ stim,
             const float* __restrict__ Wih1,   // (204,1)
             const float* __restrict__ Whh1,   // (204,51)
             const float* __restrict__ bih1,
             const float* __restrict__ bhh1,
             const float* __restrict__ Wih2,   // (4,51)
             const float* __restrict__ Whh2,   // (4,1)
             const float* __restrict__ bih2,
             const float* __restrict__ bhh2,
             float* __restrict__ out)          // (1024,2048)
{
    __shared__ __align__(16) __half hbuf[2][56];   // h1 fp16; [51..55] zero pad
    __shared__ __align__(16) float gaccf[NROWS];   // gate matvec sums (unit-major)
    __shared__ __align__(16) float x_sh[CHUNK];
    __shared__ __align__(16) float ob_sh[CHUNK];   // y(t0+dt-1)

    const int l  = threadIdx.x;
    const int n0 = blockIdx.x;

    // ---- balanced matvec rows: lane l owns rows l+32i (i=0..6, r<208) ---
    __half2 wf[7][26];
#pragma unroll
    for (int i = 0; i < 7; i++)
#pragma unroll
        for (int kk = 0; kk < 26; kk++) wf[i][kk] = __half2half2(__ushort_as_half(0));
#pragma unroll
    for (int i = 0; i < 7; i++) {
        int r = l + 32 * i;
        if (r < NROWS) {
            int u = r >> 2, g = r & 3;
            const float* src = (u < HID) ? (Whh1 + (g * HID + u) * HID)
                                         : (Wih2 + g * HID);
#pragma unroll
            for (int kk = 0; kk < 26; kk++) {
                float a = src[2*kk];
                float b = (2*kk + 1 < HID) ? src[2*kk + 1] : 0.f;
                wf[i][kk] = __floats2half2_rn(a, b);
            }
        }
    }

    // ---- owner lanes: unit A = l; unit B = l+32 (l<19) or layer-2 (l==19)
    const int  uA   = l;
    const int  uB   = l + 32;
    const bool hasB = (l < 20);
    const bool isl2 = (l == 19);
    float biasA[4], wiA[4], biasB[4], wiB[4];
#pragma unroll
    for (int g = 0; g < 4; g++) {
        const int rowA = g * HID + uA;
        biasA[g] = bih1[rowA] + bhh1[rowA];
        wiA[g]   = Wih1[rowA];
        if (l < 19) {
            const int rowB = g * HID + uB;
            biasB[g] = bih1[rowB] + bhh1[rowB];
            wiB[g]   = Wih1[rowB];
        } else if (isl2) {
            biasB[g] = bih2[g] + bhh2[g];
            wiB[g]   = Whh2[g];
        } else { biasB[g] = 0.f; wiB[g] = 0.f; }
    }

    for (int i = l; i < 56; i += NTH) ((unsigned*)hbuf)[i] = 0u;
    float cA = 0.f, cB = 0.f;          // fp32 cell states
    float h2 = 0.f;                    // layer-2 hidden (lane 19)

    if (l < 16)
        *(float4*)&x_sh[l * 4] = *(const float4*)&stim[n0 * TT + l * 4];
    __syncwarp();

#pragma unroll 1
    for (int t0 = 0; t0 < TT; t0 += CHUNK) {
#pragma unroll 2
        for (int dt = 0; dt < CHUNK; dt++) {
            const int rd = dt & 1;
            // ---- balanced matvec: 182 HFMA2 (7 rows x 26 pairs) --------
            __half2 p[26];
            {
                const uint4* h4 = (const uint4*)&hbuf[rd][0];
#pragma unroll
                for (int q = 0; q < 6; q++) {
                    uint4 v = h4[q];
                    p[4*q + 0] = *(__half2*)&v.x; p[4*q + 1] = *(__half2*)&v.y;
                    p[4*q + 2] = *(__half2*)&v.z; p[4*q + 3] = *(__half2*)&v.w;
                }
                uint2 v = ((const uint2*)h4)[12];
                p[24] = *(__half2*)&v.x; p[25] = *(__half2*)&v.y;
            }
            __half2 z = __half2half2(__ushort_as_half(0));
            __half2 acc[7] = {z, z, z, z, z, z, z};
#pragma unroll
            for (int kk = 0; kk < 26; kk++)
#pragma unroll
                for (int i = 0; i < 7; i++)
                    acc[i] = __hfma2(wf[i][kk], p[kk], acc[i]);
            // ---- scatter row sums (fp32) to unit-major slots -----------
#pragma unroll
            for (int i = 0; i < 7; i++) {
                int r = l + 32 * i;
                if (r < NROWS)
                    gaccf[r] = __half2float(hsum2(acc[i]));
            }
            __syncwarp();

            // ---- owner phase: fp32 gate finish + cell update -----------
            const float xt = x_sh[dt];
            {   // unit A (all 32 lanes)
                float4 ga = *(const float4*)&gaccf[uA * 4];
                float i0 = ga.x + fmaf(wiA[0], xt, biasA[0]);
                float f0 = ga.y + fmaf(wiA[1], xt, biasA[1]);
                float g0 = ga.z + fmaf(wiA[2], xt, biasA[2]);
                float o0 = ga.w + fmaf(wiA[3], xt, biasA[3]);
                cA = fmaf(fmaf(0.5f, tanhx(0.5f * f0), 0.5f), cA,
                          fmaf(0.5f, tanhx(0.5f * i0), 0.5f) * tanhx(g0));
                hbuf[1 - rd][uA] =
                    __float2half_rn(fmaf(0.5f, tanhx(0.5f * o0), 0.5f) * tanhx(cA));
            }
            if (hasB) {   // unit B (l<19) or layer-2 (l==19)
                float4 gb = *(const float4*)&gaccf[uB * 4];
                float xb = isl2 ? h2 : xt;
                float i0 = gb.x + fmaf(wiB[0], xb, biasB[0]);
                float f0 = gb.y + fmaf(wiB[1], xb, biasB[1]);
                float g0 = gb.z + fmaf(wiB[2], xb, biasB[2]);
                float o0 = gb.w + fmaf(wiB[3], xb, biasB[3]);
                if (!isl2) {
                    cB = fmaf(fmaf(0.5f, tanhx(0.5f * f0), 0.5f), cB,
                              fmaf(0.5f, tanhx(0.5f * i0), 0.5f) * tanhx(g0));
                    hbuf[1 - rd][uB] =
                        __float2half_rn(fmaf(0.5f, tanhx(0.5f * o0), 0.5f) * tanhx(cB));
                } else if ((t0 | dt) != 0) {       // lag-1 layer-2; skip t=0
                    cB = fmaf(fmaf(0.5f, tanhx(0.5f * f0), 0.5f), cB,
                              fmaf(0.5f, tanhx(0.5f * i0), 0.5f) * tanhx(g0));
                    float y = fmaf(0.5f, tanhx(0.5f * o0), 0.5f) * tanhx(cB);
                    ob_sh[dt] = y;
                    h2 = y;
                }
            }
            __syncwarp();
        }
        // ---- flush outputs (lagged by 1) + stage next chunk ------------
        for (int i = l; i < CHUNK; i += NTH) {
            int t = t0 - 1 + i;
            if (t >= 0) out[n0 * TT + t] = ob_sh[i];
        }
        if (t0 + CHUNK < TT && l < 16)
            *(float4*)&x_sh[l * 4] =
                *(const float4*)&stim[n0 * TT + t0 + CHUNK + l * 4];
        __syncwarp();
    }

    // ---- tail: y(2047) from h1(2047) (in hbuf[0]); lane 19 scalar ------
    if (isl2) {
        float gt[4] = {0.f, 0.f, 0.f, 0.f};
        for (int k = 0; k < HID; k++) {
            float hv = __half2float(hbuf[0][k]);
#pragma unroll
            for (int g = 0; g < 4; g++)
                gt[g] = fmaf(Wih2[g * HID + k], hv, gt[g]);
        }
#pragma unroll
        for (int g = 0; g < 4; g++)
            gt[g] += fmaf(wiB[g], h2, biasB[g]);
        cB = fmaf(fmaf(0.5f, tanhx(0.5f * gt[1]), 0.5f), cB,
                  fmaf(0.5f, tanhx(0.5f * gt[0]), 0.5f) * tanhx(gt[2]));
        out[n0 * TT + (TT - 1)] =
            fmaf(0.5f, tanhx(0.5f * gt[3]), 0.5f) * tanhx(cB);
    }
}

extern "C" void kernel_launch(void* const* d_in, const int* in_sizes, int n_in,
                              void* d_out, int out_size)
{
    (void)in_sizes; (void)n_in; (void)out_size;
    const float* stim  = (const float*)d_in[0];
    const float* Wih1  = (const float*)d_in[1];
    const float* Whh1  = (const float*)d_in[2];
    const float* bih1  = (const float*)d_in[3];
    const float* bhh1  = (const float*)d_in[4];
    const float* Wih2  = (const float*)d_in[5];
    const float* Whh2  = (const float*)d_in[6];
    const float* bih2  = (const float*)d_in[7];
    const float* bhh2  = (const float*)d_in[8];
    float* out = (float*)d_out;

    lstm2_kernel<<<NN, NTH>>>(stim, Wih1, Whh1, bih1, bhh1,
                              Wih2, Whh2, bih2, bhh2, out);
}